// round 10
// baseline (speedup 1.0000x reference)
#include <cuda_runtime.h>

// Problem constants
#define BB   1024
#define TT   512
#define II   100
#define HH   150
#define HP   160    // padded hidden (mult of 32)
#define OO   3

// Fused rnn kernel geometry
#define NKC  6      // k/i chunk count (= thread groups)
#define KC   25     // W_hh k-chunk (6*25 = 150 exactly)
#define IC   17     // W_ih i-chunk (6*17 = 102 >= 100)
#define ICP  102    // padded input dim
#define HROW 8      // hs row stride (row 7 = pad)
#define XR   12     // xstage row stride (16B-aligned float4s, 4-way STS conflict only)
#define RB   7      // batch rows per CTA (147 CTAs)

// Output tuple layout: out, hidden, logits
#define HID_OFF  ((size_t)BB * TT * OO)
#define LOG_OFF  (HID_OFF + (size_t)BB * TT * HH)

// ---------------------------------------------------------------------------
// Fused kernel: input projection + sequential RNN in ONE kernel.
// 147 CTAs x 7 batch rows, 480 threads (15 warps).
// Thread = (jp = tid%80, kc = tid/80): handles j in {jp, jp+80}.
//   - W_hh[{jp,j1}][25kc..+24] in registers (50 regs)
//   - W_ih[{jp,j1}][17kc..+16] in registers (34 regs)
// Per step: acc = Whh-partial(h(t)) + Wih-partial(x(t)) accumulated together;
// cross-kc reduction via smem psum (2 barriers/step). x(t+1) staged
// transposed in smem (double-buffered) via LDG->STS during step t.
// No g_xw scratch, no separate xw kernel, no xw gmem loads in the loop.
// ---------------------------------------------------------------------------
__global__ void __launch_bounds__(480, 1) rnn_fused_kernel(
        const float* __restrict__ x,
        const float* __restrict__ h0,
        const float* __restrict__ W_ih,
        const float* __restrict__ W_hh,
        float* __restrict__ out) {
    __shared__ __align__(16) float hs[2][HH * HROW];     // [buf][k][row]
    __shared__ __align__(16) float xstage[2][ICP * XR];  // [buf][i][row]
    __shared__ float psum[NKC][RB * HP];                 // [kc][r*HP+j]

    const int tid = threadIdx.x;
    const int jp  = tid % 80;        // j pair: {jp, jp+80}
    const int kc  = tid / 80;        // chunk id [0,6)
    const int j1  = jp + 80;
    const bool j1v = (j1 < HH);
    const int b0  = blockIdx.x * RB;
    const int nrows = (BB - b0 < RB) ? (BB - b0) : RB;

    // --- one-time: W_hh chunk into registers ---
    float w0[KC], w1[KC];
#pragma unroll
    for (int i = 0; i < KC; i++) {
        const int k = KC * kc + i;
        w0[i] = W_hh[jp * HH + k];
        w1[i] = j1v ? W_hh[j1 * HH + k] : 0.f;
    }
    // --- one-time: W_ih chunk into registers (zero-padded) ---
    float u0[IC], u1[IC];
#pragma unroll
    for (int i = 0; i < IC; i++) {
        const int gi = IC * kc + i;
        u0[i] = (gi < II) ? W_ih[jp * II + gi] : 0.f;
        u1[i] = (gi < II && j1v) ? W_ih[j1 * II + gi] : 0.f;
    }

    // --- init smem: zero hs (both bufs) and xstage (both bufs) ---
    for (int idx = tid; idx < 2 * HH * HROW; idx += 480) ((float*)hs)[idx] = 0.f;
    for (int idx = tid; idx < 2 * ICP * XR; idx += 480) ((float*)xstage)[idx] = 0.f;
    __syncthreads();
    for (int idx = tid; idx < HH * nrows; idx += 480) {
        const int k = idx / nrows, r = idx - k * nrows;
        hs[0][k * HROW + r] = h0[(b0 + r) * HH + k];
    }
    // --- prologue: stage x(0) transposed into xstage[0] ---
    {
        const int idx0 = tid, idx1 = tid + 480;
        if (idx0 < RB * II) {
            const int r = idx0 / II, i = idx0 - r * II;
            const float v = (r < nrows) ? x[((size_t)(b0 + r) * TT + 0) * II + i] : 0.f;
            xstage[0][i * XR + r] = v;
        }
        if (idx1 < RB * II) {
            const int r = idx1 / II, i = idx1 - r * II;
            const float v = (r < nrows) ? x[((size_t)(b0 + r) * TT + 0) * II + i] : 0.f;
            xstage[0][i * XR + r] = v;
        }
    }
    __syncthreads();

    // reduction rows: kc owns row kc; kc==0 additionally owns row 6.
    const int r_lo = kc;
    const bool own_hi = (kc == 0);
    const int r_hi = 6;
    const bool v_lo = (r_lo < nrows);
    const bool v_hi = own_hi && (r_hi < nrows);

    float* hid_out = out + HID_OFF;
    int cur = 0;

    for (int t = 0; t < TT; t++) {
        // --- issue LDG for x(t+1) early (latency hidden by FMA phase) ---
        float xld0 = 0.f, xld1 = 0.f;
        const int idx0 = tid, idx1 = tid + 480;
        const int s0r = idx0 / II, s0i = idx0 - s0r * II;
        const int s1r = idx1 / II, s1i = idx1 - s1r * II;
        if (t + 1 < TT) {
            if (idx0 < RB * II && s0r < nrows)
                xld0 = x[((size_t)(b0 + s0r) * TT + (t + 1)) * II + s0i];
            if (idx1 < RB * II && s1r < nrows)
                xld1 = x[((size_t)(b0 + s1r) * TT + (t + 1)) * II + s1i];
        }

        float a0 = 0.f, a1 = 0.f, a2 = 0.f, a3 = 0.f, a4 = 0.f, a5 = 0.f, a6 = 0.f;
        float c0 = 0.f, c1 = 0.f, c2 = 0.f, c3 = 0.f, c4 = 0.f, c5 = 0.f, c6 = 0.f;

        // --- W_hh partial: 2 j's x 7 rows x 25 k; h broadcast from smem ---
        const float* hc = &hs[cur][(KC * kc) * HROW];
#pragma unroll
        for (int i = 0; i < KC; i++) {
            const float4 va = *(const float4*)(hc + i * HROW);       // rows 0-3
            const float4 vb = *(const float4*)(hc + i * HROW + 4);   // rows 4-6
            a0 = fmaf(w0[i], va.x, a0);  c0 = fmaf(w1[i], va.x, c0);
            a1 = fmaf(w0[i], va.y, a1);  c1 = fmaf(w1[i], va.y, c1);
            a2 = fmaf(w0[i], va.z, a2);  c2 = fmaf(w1[i], va.z, c2);
            a3 = fmaf(w0[i], va.w, a3);  c3 = fmaf(w1[i], va.w, c3);
            a4 = fmaf(w0[i], vb.x, a4);  c4 = fmaf(w1[i], vb.x, c4);
            a5 = fmaf(w0[i], vb.y, a5);  c5 = fmaf(w1[i], vb.y, c5);
            a6 = fmaf(w0[i], vb.z, a6);  c6 = fmaf(w1[i], vb.z, c6);
        }

        // --- W_ih partial: same accumulators; x(t) broadcast from smem ---
        const float* xc = &xstage[t & 1][(IC * kc) * XR];
#pragma unroll
        for (int i = 0; i < IC; i++) {
            const float4 va = *(const float4*)(xc + i * XR);         // rows 0-3
            const float4 vb = *(const float4*)(xc + i * XR + 4);     // rows 4-6
            a0 = fmaf(u0[i], va.x, a0);  c0 = fmaf(u1[i], va.x, c0);
            a1 = fmaf(u0[i], va.y, a1);  c1 = fmaf(u1[i], va.y, c1);
            a2 = fmaf(u0[i], va.z, a2);  c2 = fmaf(u1[i], va.z, c2);
            a3 = fmaf(u0[i], va.w, a3);  c3 = fmaf(u1[i], va.w, c3);
            a4 = fmaf(u0[i], vb.x, a4);  c4 = fmaf(u1[i], vb.x, c4);
            a5 = fmaf(u0[i], vb.y, a5);  c5 = fmaf(u1[i], vb.y, c5);
            a6 = fmaf(u0[i], vb.z, a6);  c6 = fmaf(u1[i], vb.z, c6);
        }

        // --- store x(t+1) into the other xstage buffer ---
        if (t + 1 < TT) {
            if (idx0 < RB * II) xstage[(t + 1) & 1][s0i * XR + s0r] = xld0;
            if (idx1 < RB * II) xstage[(t + 1) & 1][s1i * XR + s1r] = xld1;
        }

        // --- write partials (both j's) ---
        float* ps = psum[kc] + jp;
        ps[0 * HP] = a0; ps[1 * HP] = a1; ps[2 * HP] = a2; ps[3 * HP] = a3;
        ps[4 * HP] = a4; ps[5 * HP] = a5; ps[6 * HP] = a6;
        float* ps1 = ps + 80;
        ps1[0 * HP] = c0; ps1[1 * HP] = c1; ps1[2 * HP] = c2; ps1[3 * HP] = c3;
        ps1[4 * HP] = c4; ps1[5 * HP] = c5; ps1[6 * HP] = c6;
        __syncthreads();

        // --- reduce owned rows across 6 chunk partials, relu (no xw loads) ---
        float s00 = psum[0][r_lo * HP + jp] + psum[1][r_lo * HP + jp]
                  + psum[2][r_lo * HP + jp] + psum[3][r_lo * HP + jp]
                  + psum[4][r_lo * HP + jp] + psum[5][r_lo * HP + jp];
        float s01 = psum[0][r_lo * HP + j1] + psum[1][r_lo * HP + j1]
                  + psum[2][r_lo * HP + j1] + psum[3][r_lo * HP + j1]
                  + psum[4][r_lo * HP + j1] + psum[5][r_lo * HP + j1];
        s00 = fmaxf(s00, 0.f);
        s01 = fmaxf(s01, 0.f);
        float s10 = 0.f, s11 = 0.f;
        if (own_hi) {
            s10 = psum[0][r_hi * HP + jp] + psum[1][r_hi * HP + jp]
                + psum[2][r_hi * HP + jp] + psum[3][r_hi * HP + jp]
                + psum[4][r_hi * HP + jp] + psum[5][r_hi * HP + jp];
            s11 = psum[0][r_hi * HP + j1] + psum[1][r_hi * HP + j1]
                + psum[2][r_hi * HP + j1] + psum[3][r_hi * HP + j1]
                + psum[4][r_hi * HP + j1] + psum[5][r_hi * HP + j1];
            s10 = fmaxf(s10, 0.f);
            s11 = fmaxf(s11, 0.f);
        }

        // --- write next h state (transposed) + hidden output ---
        float* hn = hs[cur ^ 1];
        hn[jp * HROW + r_lo] = s00;
        if (j1v) hn[j1 * HROW + r_lo] = s01;
        if (v_lo) {
            hid_out[((size_t)(b0 + r_lo) * TT + t) * HH + jp] = s00;
            if (j1v) hid_out[((size_t)(b0 + r_lo) * TT + t) * HH + j1] = s01;
        }
        if (own_hi) {
            hn[jp * HROW + r_hi] = s10;
            if (j1v) hn[j1 * HROW + r_hi] = s11;
            if (v_hi) {
                hid_out[((size_t)(b0 + r_hi) * TT + t) * HH + jp] = s10;
                if (j1v) hid_out[((size_t)(b0 + r_hi) * TT + t) * HH + j1] = s11;
            }
        }

        __syncthreads();
        cur ^= 1;
    }
}

// ---------------------------------------------------------------------------
// Kernel 2: logits = hidden @ W_fc^T; out = one_hot(argmax(logits+g)).
// ---------------------------------------------------------------------------
__global__ void __launch_bounds__(256) post_kernel(const float* __restrict__ g,
                                                   const float* __restrict__ W_fc,
                                                   float* __restrict__ out) {
    __shared__ float wfc[OO * HP];
    const int tid = threadIdx.x;
    for (int i = tid; i < OO * HP; i += 256) {
        const int o = i / HP, k = i - o * HP;
        wfc[i] = (k < HH) ? W_fc[o * HH + k] : 0.f;
    }
    __syncthreads();

    const int warp = tid >> 5, lane = tid & 31;
    const size_t bt = (size_t)blockIdx.x * 8 + warp;
    const float* hid = out + HID_OFF + bt * HH;

    float hv[5];
#pragma unroll
    for (int m = 0; m < 5; m++) {
        const int k = lane + 32 * m;
        hv[m] = (k < HH) ? hid[k] : 0.f;
    }
    float p[OO];
#pragma unroll
    for (int o = 0; o < OO; o++) {
        float s = 0.f;
#pragma unroll
        for (int m = 0; m < 5; m++)
            s = fmaf(hv[m], wfc[o * HP + lane + 32 * m], s);
#pragma unroll
        for (int off = 16; off > 0; off >>= 1)
            s += __shfl_xor_sync(0xffffffffu, s, off);
        p[o] = s;
    }
    if (lane == 0) {
        const float z0 = p[0] + g[bt * OO + 0];
        const float z1 = p[1] + g[bt * OO + 1];
        const float z2 = p[2] + g[bt * OO + 2];
        int idx = 0; float best = z0;
        if (z1 > best) { best = z1; idx = 1; }
        if (z2 > best) { best = z2; idx = 2; }
        float* op = out + bt * OO;
        op[0] = (idx == 0) ? 1.f : 0.f;
        op[1] = (idx == 1) ? 1.f : 0.f;
        op[2] = (idx == 2) ? 1.f : 0.f;
        float* lp = out + LOG_OFF + bt * OO;
        lp[0] = p[0]; lp[1] = p[1]; lp[2] = p[2];
    }
}

// ---------------------------------------------------------------------------
extern "C" void kernel_launch(void* const* d_in, const int* in_sizes, int n_in,
                              void* d_out, int out_size) {
    const float* x    = (const float*)d_in[0];
    const float* h0   = (const float*)d_in[1];
    const float* g    = (const float*)d_in[2];
    const float* W_ih = (const float*)d_in[3];
    const float* W_hh = (const float*)d_in[4];
    const float* W_fc = (const float*)d_in[5];
    float* out = (float*)d_out;

    rnn_fused_kernel<<<(BB + RB - 1) / RB, 480>>>(x, h0, W_ih, W_hh, out);  // 147 CTAs
    post_kernel<<<(BB * TT) / 8, 256>>>(g, W_fc, out);
}

// round 12
// speedup vs baseline: 1.1360x; 1.1360x over previous
#include <cuda_runtime.h>

// Problem constants
#define BB   1024
#define TT   512
#define II   100
#define IIP  104    // padded input row stride (floats)
#define HH   150
#define HP   160    // padded hidden (mult of 32)
#define OO   3
#define WP   161    // weight smem pitch
#define XT   32     // xw rows per tile

// rnn kernel geometry: 8-way k split x 2 j's per thread, 640 threads
#define NKC  8
#define KC   19     // 8*19 = 152 >= 150
#define HSK  152    // padded k extent of hs
#define HROW 8      // hs row stride (row 7 = pad)
#define RB   7      // batch rows per rnn CTA (147 CTAs)

// Output tuple layout: out, hidden, logits
#define HID_OFF  ((size_t)BB * TT * OO)
#define LOG_OFF  (HID_OFF + (size_t)BB * TT * HH)

// Scratch: input projection xw[bt][HP] (~335 MB)
__device__ float g_xw[(size_t)BB * TT * HP];

__device__ __forceinline__ unsigned smem_u32(const void* p) {
    return (unsigned)__cvta_generic_to_shared(p);
}

// ---------------------------------------------------------------------------
// Kernel 1: xw[bt][j] = sum_i x[bt][i] * W_ih[j][i].
// R7 design verbatim (measured 493us).
// ---------------------------------------------------------------------------
__global__ void __launch_bounds__(320, 2) xw_kernel(const float* __restrict__ x,
                                                    const float* __restrict__ W_ih) {
    extern __shared__ float sm[];
    float* WihT = sm;                 // [II][WP]
    float* xs0  = sm + II * WP;       // [XT][IIP]
    float* xs1  = xs0 + XT * IIP;     // [XT][IIP]
    const int tid = threadIdx.x;

    for (int i = tid; i < II * WP; i += 320) WihT[i] = 0.f;
    __syncthreads();
    for (int idx = tid; idx < HH * II; idx += 320) {
        const int h = idx / II, i = idx - h * II;
        WihT[i * WP + h] = W_ih[idx];
    }

    const int jp   = tid % 80;        // j pair: {jp, jp+80}
    const int half = tid / 80;        // rows half*8 .. half*8+7
    const int nTiles = (BB * TT) / XT;

    auto stage = [&](float* dst, int tile) {
        const int bt0 = tile * XT;
#pragma unroll
        for (int s = 0; s < 3; s++) {
            const int c = tid + s * 320;
            if (c < XT * 25) {
                const int r = c / 25, k = c - r * 25;
                const float* src = x + (size_t)(bt0 + r) * II + k * 4;
                const unsigned d = smem_u32(dst + r * IIP + k * 4);
                asm volatile("cp.async.ca.shared.global [%0], [%1], 16;"
                             :: "r"(d), "l"(src));
            }
        }
    };

    stage(xs0, blockIdx.x);
    asm volatile("cp.async.commit_group;");
    asm volatile("cp.async.wait_group 0;");
    __syncthreads();

    int buf = 0;
    for (int tile = blockIdx.x; tile < nTiles; tile += gridDim.x) {
        const int next = tile + gridDim.x;
        float* cur = buf ? xs1 : xs0;
        float* oth = buf ? xs0 : xs1;
        if (next < nTiles) stage(oth, next);
        asm volatile("cp.async.commit_group;");

        const int bt0 = tile * XT;
        float acc0[8], acc1[8];
#pragma unroll
        for (int r = 0; r < 8; r++) { acc0[r] = 0.f; acc1[r] = 0.f; }

        const float* xrow = cur + half * 8 * IIP;
#pragma unroll
        for (int kq = 0; kq < II / 4; kq++) {
            const float wa0 = WihT[(4 * kq + 0) * WP + jp];
            const float wa1 = WihT[(4 * kq + 1) * WP + jp];
            const float wa2 = WihT[(4 * kq + 2) * WP + jp];
            const float wa3 = WihT[(4 * kq + 3) * WP + jp];
            const float wb0 = WihT[(4 * kq + 0) * WP + jp + 80];
            const float wb1 = WihT[(4 * kq + 1) * WP + jp + 80];
            const float wb2 = WihT[(4 * kq + 2) * WP + jp + 80];
            const float wb3 = WihT[(4 * kq + 3) * WP + jp + 80];
#pragma unroll
            for (int r = 0; r < 8; r++) {
                const float4 xv = *(const float4*)&xrow[r * IIP + 4 * kq];  // broadcast
                acc0[r] = fmaf(xv.x, wa0, acc0[r]);
                acc0[r] = fmaf(xv.y, wa1, acc0[r]);
                acc0[r] = fmaf(xv.z, wa2, acc0[r]);
                acc0[r] = fmaf(xv.w, wa3, acc0[r]);
                acc1[r] = fmaf(xv.x, wb0, acc1[r]);
                acc1[r] = fmaf(xv.y, wb1, acc1[r]);
                acc1[r] = fmaf(xv.z, wb2, acc1[r]);
                acc1[r] = fmaf(xv.w, wb3, acc1[r]);
            }
        }
#pragma unroll
        for (int r = 0; r < 8; r++) {
            const size_t row = (size_t)(bt0 + half * 8 + r);
            g_xw[row * HP + jp]      = acc0[r];
            g_xw[row * HP + jp + 80] = acc1[r];
        }

        asm volatile("cp.async.wait_group 0;");
        __syncthreads();
        buf ^= 1;
    }
}

// ---------------------------------------------------------------------------
// Kernel 2: sequential RNN. 147 CTAs x 7 rows, 640 threads (20 warps,
// 5/5/5/5 SMSP balance). Thread = (jp = tid%80, kc = tid/80 in [0,8)):
// two j's {jp, jp+80}, W_hh[{jp,j1}][19kc..+18] in registers (~77 regs).
// Warp-uniform broadcast LDS in the FMA loop (load-bearing).
// Cross-kc reduction via smem psum, 2 barriers/step. kc<7 owns row kc.
// NOTE: px0 row CLAMPED to a valid batch row when r_lo >= nrows (last CTA)
// — this was the R11 OOB bug.
// ---------------------------------------------------------------------------
__global__ void __launch_bounds__(640, 1) rnn_kernel(const float* __restrict__ h0,
                                                     const float* __restrict__ W_hh,
                                                     float* __restrict__ out) {
    __shared__ __align__(16) float hs[2][HSK * HROW];  // [buf][k][row]
    __shared__ float psum[NKC][RB * HP];                // [kc][r*HP+j]

    const int tid = threadIdx.x;
    const int jp  = tid % 80;        // j pair: {jp, jp+80}
    const int kc  = tid / 80;        // [0,8)
    const int j1  = jp + 80;
    const bool j1v = (j1 < HH);      // jp < 70
    const int b0  = blockIdx.x * RB;
    const int nrows = (BB - b0 < RB) ? (BB - b0) : RB;

    // --- one-time: weights into registers (zero-pad k >= 150) ---
    float w0[KC], w1[KC];
#pragma unroll
    for (int i = 0; i < KC; i++) {
        const int k = KC * kc + i;
        w0[i] = (k < HH) ? W_hh[jp * HH + k] : 0.f;
        w1[i] = (k < HH && j1v) ? W_hh[j1 * HH + k] : 0.f;
    }

    // --- init hs: zero both buffers (covers pad rows/k), fill h0 ---
    for (int idx = tid; idx < 2 * HSK * HROW; idx += 640) ((float*)hs)[idx] = 0.f;
    __syncthreads();
    for (int idx = tid; idx < HH * nrows; idx += 640) {
        const int k = idx / nrows, r = idx - k * nrows;
        hs[0][k * HROW + r] = h0[(b0 + r) * HH + k];
    }
    __syncthreads();

    // ownership: kc < 7 owns row kc (if within this CTA's batch rows).
    const int r_red = (kc < RB) ? kc : 0;          // row this thread reduces
    const bool own  = (kc < RB) && (r_red < nrows); // valid output row?
    const int r_ld  = own ? r_red : 0;              // CLAMPED row for gmem prefetch
    const float* px0 = g_xw + ((size_t)(b0 + r_ld) * TT) * HP + jp;
    float xw00 = px0[0], xw01 = px0[80];

    float* hid_out = out + HID_OFF;
    int cur = 0;

    for (int t = 0; t < TT; t++) {
        // prefetch next step's xw (latency hidden by FMA loop)
        float n00 = 0.f, n01 = 0.f;
        if (t + 1 < TT) { n00 = px0[HP]; n01 = px0[HP + 80]; }

        // --- main FMA loop: 2 j's x 7 rows x 19 k; h broadcast from smem ---
        const float* hc = &hs[cur][(KC * kc) * HROW];
        float a0 = 0.f, a1 = 0.f, a2 = 0.f, a3 = 0.f, a4 = 0.f, a5 = 0.f, a6 = 0.f;
        float c0 = 0.f, c1 = 0.f, c2 = 0.f, c3 = 0.f, c4 = 0.f, c5 = 0.f, c6 = 0.f;
#pragma unroll
        for (int i = 0; i < KC; i++) {
            const float4 va = *(const float4*)(hc + i * HROW);       // rows 0-3
            const float4 vb = *(const float4*)(hc + i * HROW + 4);   // rows 4-6
            a0 = fmaf(w0[i], va.x, a0);  c0 = fmaf(w1[i], va.x, c0);
            a1 = fmaf(w0[i], va.y, a1);  c1 = fmaf(w1[i], va.y, c1);
            a2 = fmaf(w0[i], va.z, a2);  c2 = fmaf(w1[i], va.z, c2);
            a3 = fmaf(w0[i], va.w, a3);  c3 = fmaf(w1[i], va.w, c3);
            a4 = fmaf(w0[i], vb.x, a4);  c4 = fmaf(w1[i], vb.x, c4);
            a5 = fmaf(w0[i], vb.y, a5);  c5 = fmaf(w1[i], vb.y, c5);
            a6 = fmaf(w0[i], vb.z, a6);  c6 = fmaf(w1[i], vb.z, c6);
        }

        // --- write partials (both j's) ---
        float* ps = psum[kc] + jp;
        ps[0 * HP] = a0; ps[1 * HP] = a1; ps[2 * HP] = a2; ps[3 * HP] = a3;
        ps[4 * HP] = a4; ps[5 * HP] = a5; ps[6 * HP] = a6;
        float* ps1 = ps + 80;
        ps1[0 * HP] = c0; ps1[1 * HP] = c1; ps1[2 * HP] = c2; ps1[3 * HP] = c3;
        ps1[4 * HP] = c4; ps1[5 * HP] = c5; ps1[6 * HP] = c6;
        __syncthreads();

        // --- reduce owned row across 8 kc partials + xw, relu ---
        if (kc < RB) {
            float s00 = psum[0][r_red * HP + jp] + psum[1][r_red * HP + jp]
                      + psum[2][r_red * HP + jp] + psum[3][r_red * HP + jp]
                      + psum[4][r_red * HP + jp] + psum[5][r_red * HP + jp]
                      + psum[6][r_red * HP + jp] + psum[7][r_red * HP + jp] + xw00;
            float s01 = psum[0][r_red * HP + j1] + psum[1][r_red * HP + j1]
                      + psum[2][r_red * HP + j1] + psum[3][r_red * HP + j1]
                      + psum[4][r_red * HP + j1] + psum[5][r_red * HP + j1]
                      + psum[6][r_red * HP + j1] + psum[7][r_red * HP + j1] + xw01;
            s00 = fmaxf(s00, 0.f);
            s01 = fmaxf(s01, 0.f);

            // write next h state (transposed) + hidden output
            float* hn = hs[cur ^ 1];
            hn[jp * HROW + r_red] = s00;
            if (j1v) hn[j1 * HROW + r_red] = s01;
            if (own) {
                hid_out[((size_t)(b0 + r_red) * TT + t) * HH + jp] = s00;
                if (j1v) hid_out[((size_t)(b0 + r_red) * TT + t) * HH + j1] = s01;
            }
        }

        xw00 = n00; xw01 = n01;
        px0 += HP;
        __syncthreads();
        cur ^= 1;
    }
}

// ---------------------------------------------------------------------------
// Kernel 3: logits = hidden @ W_fc^T; out = one_hot(argmax(logits+g)).
// Each warp processes 4 bt rows; all 20 hidden loads prefetched first.
// ---------------------------------------------------------------------------
__global__ void __launch_bounds__(256) post_kernel(const float* __restrict__ g,
                                                   const float* __restrict__ W_fc,
                                                   float* __restrict__ out) {
    __shared__ float wfc[OO * HP];
    const int tid = threadIdx.x;
    for (int i = tid; i < OO * HP; i += 256) {
        const int o = i / HP, k = i - o * HP;
        wfc[i] = (k < HH) ? W_fc[o * HH + k] : 0.f;
    }
    __syncthreads();

    const int warp = tid >> 5, lane = tid & 31;
    const size_t bt0 = ((size_t)blockIdx.x * 8 + warp) * 4;
    const float* hid = out + HID_OFF;

    // prefetch all 4 rows x 5 chunks (20 independent LDGs in flight)
    float hv[4][5];
#pragma unroll
    for (int u = 0; u < 4; u++) {
        const float* hrow = hid + (bt0 + u) * HH;
#pragma unroll
        for (int m = 0; m < 5; m++) {
            const int k = lane + 32 * m;
            hv[u][m] = (k < HH) ? hrow[k] : 0.f;
        }
    }

#pragma unroll
    for (int u = 0; u < 4; u++) {
        const size_t bt = bt0 + u;
        float p[OO];
#pragma unroll
        for (int o = 0; o < OO; o++) {
            float s = 0.f;
#pragma unroll
            for (int m = 0; m < 5; m++)
                s = fmaf(hv[u][m], wfc[o * HP + lane + 32 * m], s);
#pragma unroll
            for (int off = 16; off > 0; off >>= 1)
                s += __shfl_xor_sync(0xffffffffu, s, off);
            p[o] = s;
        }
        if (lane == 0) {
            const float z0 = p[0] + g[bt * OO + 0];
            const float z1 = p[1] + g[bt * OO + 1];
            const float z2 = p[2] + g[bt * OO + 2];
            int idx = 0; float best = z0;
            if (z1 > best) { best = z1; idx = 1; }
            if (z2 > best) { best = z2; idx = 2; }
            float* op = out + bt * OO;
            op[0] = (idx == 0) ? 1.f : 0.f;
            op[1] = (idx == 1) ? 1.f : 0.f;
            op[2] = (idx == 2) ? 1.f : 0.f;
            float* lp = out + LOG_OFF + bt * OO;
            lp[0] = p[0]; lp[1] = p[1]; lp[2] = p[2];
        }
    }
}

// ---------------------------------------------------------------------------
extern "C" void kernel_launch(void* const* d_in, const int* in_sizes, int n_in,
                              void* d_out, int out_size) {
    const float* x    = (const float*)d_in[0];
    const float* h0   = (const float*)d_in[1];
    const float* g    = (const float*)d_in[2];
    const float* W_ih = (const float*)d_in[3];
    const float* W_hh = (const float*)d_in[4];
    const float* W_fc = (const float*)d_in[5];
    float* out = (float*)d_out;

    const int xw_smem = (II * WP + 2 * XT * IIP) * (int)sizeof(float);   // ~91 KB
    cudaFuncSetAttribute(xw_kernel, cudaFuncAttributeMaxDynamicSharedMemorySize, xw_smem);

    xw_kernel<<<2048, 320, xw_smem>>>(x, W_ih);
    rnn_kernel<<<(BB + RB - 1) / RB, 640>>>(h0, W_hh, out);   // 147 CTAs
    post_kernel<<<(BB * TT) / 32, 256>>>(g, W_fc, out);       // 16384 blocks
}